// round 4
// baseline (speedup 1.0000x reference)
#include <cuda_runtime.h>

#define ULL unsigned long long

// ---------------- scratch (static device allocations) ----------------
__device__ float g_Qp[256 * 9216];   // Q'[f][p] = kA[f] * Qs[f][p]
__device__ float g_V[64 * 9216];     // V[c][p]
__device__ float g_cA[8 * 256];
__device__ float g_cB[256];
__device__ float g_cC[256];

// ---------------- packed f32x2 helpers ----------------
__device__ __forceinline__ ULL pack2(float lo, float hi) {
    ULL r;
    asm("mov.b64 %0, {%1, %2};" : "=l"(r)
        : "r"(__float_as_uint(lo)), "r"(__float_as_uint(hi)));
    return r;
}
__device__ __forceinline__ void unpack2(ULL v, float& lo, float& hi) {
    unsigned a, b;
    asm("mov.b64 {%0, %1}, %2;" : "=r"(a), "=r"(b) : "l"(v));
    lo = __uint_as_float(a);
    hi = __uint_as_float(b);
}
__device__ __forceinline__ void fma2(ULL& d, ULL a, ULL b) {
    asm("fma.rn.f32x2 %0, %1, %2, %0;" : "+l"(d) : "l"(a), "l"(b));
}
__device__ __forceinline__ void mul2(ULL& d, ULL a) {
    asm("mul.rn.f32x2 %0, %0, %1;" : "+l"(d) : "l"(a));
}

// ---------------- kernel 1: per-feature coefficients ----------------
__global__ void coef_kernel(const float* __restrict__ WQ_task,
                            const float* __restrict__ BQ_task,
                            const float* __restrict__ WK_task,
                            const float* __restrict__ WQ_tm1,
                            const float* __restrict__ WQ_x,
                            const float* __restrict__ BQ,
                            const float* __restrict__ WK_x) {
    int f = threadIdx.x;  // 256 threads
    float kA = WK_task[f] * WK_x[f];
    float sW = 0.f, sB = 0.f;
#pragma unroll
    for (int h = 0; h < 8; h++) {
        float wq = WQ_task[h * 256 + f];
        sW += wq;
        sB += wq * BQ[h * 256 + f] + BQ_task[h * 256 + f];
        g_cA[h * 256 + f] = kA * wq * WQ_tm1[h * 256 + f];
    }
    g_cB[f] = kA * WQ_x[f] * sW;
    g_cC[f] = kA * sB;
}

// ---------------- kernel 2: build Q' = kA * (sum_h a prevQ + b X + c) ----------------
__global__ void qprep_kernel(const float* __restrict__ X,
                             const float* __restrict__ prevQ) {
    int f = blockIdx.y;
    int p = blockIdx.x * 256 + threadIdx.x;
    float q = fmaf(g_cB[f], X[f * 9216 + p], g_cC[f]);
#pragma unroll
    for (int h = 0; h < 8; h++)
        q = fmaf(g_cA[h * 256 + f], prevQ[(h * 256 + f) * 9216 + p], q);
    g_Qp[f * 9216 + p] = q;
}

// ---------------- kernel 3: 3x3 SAME conv (F=256 -> C=64) + affine ----------------
// grid: (96 w-rows, 2 c-halves); block 256 threads.
// thread: c = cbase + tid/8, h0 = (tid%8)*12, computes 12 h outputs.
__global__ void __launch_bounds__(256) conv_kernel(const float* __restrict__ X,
                                                   const float* __restrict__ Wc,
                                                   const float* __restrict__ Bc,
                                                   const float* __restrict__ WV,
                                                   const float* __restrict__ BV) {
    __shared__ float sx[4 * 294];  // [4 f][3 dw][98 h (padded)]
    __shared__ float sw[4 * 288];  // [4 f][32 c][9 taps]
    const int tid = threadIdx.x;
    const int w = blockIdx.x;
    const int cbase = blockIdx.y * 32;
    const int cl = tid >> 3;
    const int c = cbase + cl;
    const int h0 = (tid & 7) * 12;

    float acc[12];
#pragma unroll
    for (int i = 0; i < 12; i++) acc[i] = 0.f;

    for (int fc = 0; fc < 256; fc += 4) {
        __syncthreads();
        for (int i = tid; i < 4 * 294; i += 256) {
            int ff = i / 294, r = i % 294;
            int dw = r / 98, hh = r % 98;
            int ww = w + dw - 1;
            float v = 0.f;
            if (ww >= 0 && ww < 96 && hh >= 1 && hh <= 96)
                v = X[(fc + ff) * 9216 + ww * 96 + hh - 1];
            sx[i] = v;
        }
        for (int i = tid; i < 4 * 288; i += 256) {
            int ff = i / 288, r = i % 288;
            int ccl = r / 9, s = r % 9;
            sw[i] = Wc[((cbase + ccl) * 256 + fc + ff) * 9 + s];
        }
        __syncthreads();
#pragma unroll
        for (int ff = 0; ff < 4; ff++) {
            float wv[9];
#pragma unroll
            for (int s = 0; s < 9; s++) wv[s] = sw[ff * 288 + cl * 9 + s];
#pragma unroll
            for (int dw = 0; dw < 3; dw++) {
                float xr[14];
#pragma unroll
                for (int j = 0; j < 14; j++) xr[j] = sx[ff * 294 + dw * 98 + h0 + j];
#pragma unroll
                for (int hi = 0; hi < 12; hi++)
#pragma unroll
                    for (int dh = 0; dh < 3; dh++)
                        acc[hi] = fmaf(xr[hi + dh], wv[dw * 3 + dh], acc[hi]);
            }
        }
    }
    float wv_ = WV[c], bv_ = BV[c], bc_ = Bc[c];
#pragma unroll
    for (int hi = 0; hi < 12; hi++)
        g_V[c * 9216 + w * 96 + h0 + hi] = fmaf(wv_, acc[hi] + bc_, bv_);
}

// ---------------- kernel 4: flash attention, fp32, f32x2 FMA ----------------
// grid 144 (one 64-query tile each), 256 threads (16x16, 4x4 per thread).
// smem: sQ[256][64] (64KB) | sX[64][64] (16KB) | sPT[64][68] | sVT[64][68]
static const int ATTN_SMEM_BYTES = (16384 + 4096 + 4352 + 4352) * 4;

__global__ void __launch_bounds__(256, 1)
attn_kernel(const float* __restrict__ X, float* __restrict__ out) {
    extern __shared__ float sm[];
    float* sQ = sm;             // 16384 floats
    float* sX = sm + 16384;     // 4096
    float* sPT = sm + 20480;    // 64 * 68
    float* sVT = sm + 24832;    // 64 * 68

    const int tid = threadIdx.x;
    const int ty = tid >> 4;    // 0..15 (query rows ty*4..+3)
    const int tx = tid & 15;    // 0..15 (key cols / out channels tx*4..+3)
    const int p0 = blockIdx.x * 64;

    // stage the CTA's Q' tile (256 f x 64 q) once
    for (int i = tid; i < 16384; i += 256) {
        int f = i >> 6, q = i & 63;
        sQ[i] = g_Qp[f * 9216 + p0 + q];
    }

    ULL acc2[2][4];
#pragma unroll
    for (int r = 0; r < 2; r++)
#pragma unroll
        for (int j = 0; j < 4; j++) acc2[r][j] = 0ULL;
    float m[4], l[4];
#pragma unroll
    for (int i = 0; i < 4; i++) { m[i] = -1e30f; l[i] = 0.f; }

    // prefetch first X chunk (kt=0, fcb=0) into registers
    float rx[16];
#pragma unroll
    for (int t = 0; t < 16; t++) {
        int i = tid + t * 256;
        rx[t] = X[(i >> 6) * 9216 + (i & 63)];
    }

    for (int kt = 0; kt < 144; kt++) {
        const int q0 = kt * 64;

        ULL S2[2][4];
#pragma unroll
        for (int r = 0; r < 2; r++)
#pragma unroll
            for (int j = 0; j < 4; j++) S2[r][j] = 0ULL;

        for (int fcb = 0; fcb < 4; fcb++) {
            __syncthreads();  // previous consumers of sX done
#pragma unroll
            for (int t = 0; t < 16; t++) sX[tid + t * 256] = rx[t];
            __syncthreads();  // sX visible

            // prefetch next chunk (possibly next key tile) — hides L2 latency under compute
            int nkt = kt, nfc = fcb + 1;
            if (nfc == 4) { nfc = 0; nkt = kt + 1; }
            if (nkt < 144) {
#pragma unroll
                for (int t = 0; t < 16; t++) {
                    int i = tid + t * 256;
                    rx[t] = X[(nfc * 64 + (i >> 6)) * 9216 + nkt * 64 + (i & 63)];
                }
            }

            const float* sQb = sQ + fcb * 64 * 64;
#pragma unroll 16
            for (int fl = 0; fl < 64; fl++) {
                ulonglong2 a = *(const ulonglong2*)(sQb + fl * 64 + ty * 4);
                float4 b = *(const float4*)(sX + fl * 64 + tx * 4);
                ULL b0 = pack2(b.x, b.x), b1 = pack2(b.y, b.y);
                ULL b2 = pack2(b.z, b.z), b3 = pack2(b.w, b.w);
                fma2(S2[0][0], a.x, b0); fma2(S2[1][0], a.y, b0);
                fma2(S2[0][1], a.x, b1); fma2(S2[1][1], a.y, b1);
                fma2(S2[0][2], a.x, b2); fma2(S2[1][2], a.y, b2);
                fma2(S2[0][3], a.x, b3); fma2(S2[1][3], a.y, b3);
            }
        }

        // stage V tile (transposed) — overlaps the softmax below
        for (int i = tid; i < 4096; i += 256) {
            int c = i >> 6, k = i & 63;
            sVT[k * 68 + c] = g_V[c * 9216 + q0 + k];
        }

        // ---- online softmax on the 64x64 S tile ----
        float s[4][4];
#pragma unroll
        for (int r = 0; r < 2; r++)
#pragma unroll
            for (int j = 0; j < 4; j++)
                unpack2(S2[r][j], s[2 * r][j], s[2 * r + 1][j]);

        float p_[4][4], sc[4];
#pragma unroll
        for (int i = 0; i < 4; i++) {
            float rm = fmaxf(fmaxf(s[i][0], s[i][1]), fmaxf(s[i][2], s[i][3]));
#pragma unroll
            for (int o = 8; o > 0; o >>= 1)
                rm = fmaxf(rm, __shfl_xor_sync(0xffffffffu, rm, o));
            float mn = fmaxf(m[i], rm);
            float r0 = 0.f;
#pragma unroll
            for (int j = 0; j < 4; j++) {
                p_[i][j] = __expf(s[i][j] - mn);
                r0 += p_[i][j];
            }
#pragma unroll
            for (int o = 8; o > 0; o >>= 1)
                r0 += __shfl_xor_sync(0xffffffffu, r0, o);
            sc[i] = __expf(m[i] - mn);
            l[i] = fmaf(l[i], sc[i], r0);
            m[i] = mn;
        }
        ULL sc2[2] = { pack2(sc[0], sc[1]), pack2(sc[2], sc[3]) };
#pragma unroll
        for (int r = 0; r < 2; r++)
#pragma unroll
            for (int j = 0; j < 4; j++) mul2(acc2[r][j], sc2[r]);

        // write P transposed: sPT[k][q]
#pragma unroll
        for (int j = 0; j < 4; j++) {
            float4 v = make_float4(p_[0][j], p_[1][j], p_[2][j], p_[3][j]);
            *(float4*)(sPT + (tx * 4 + j) * 68 + ty * 4) = v;
        }
        __syncthreads();  // sPT + sVT ready

        // ---- PV: acc[q][c] += sum_k P[k][q] * V[k][c] ----
#pragma unroll 16
        for (int k = 0; k < 64; k++) {
            ulonglong2 pp = *(const ulonglong2*)(sPT + k * 68 + ty * 4);
            float4 v = *(const float4*)(sVT + k * 68 + tx * 4);
            ULL v0 = pack2(v.x, v.x), v1 = pack2(v.y, v.y);
            ULL v2 = pack2(v.z, v.z), v3 = pack2(v.w, v.w);
            fma2(acc2[0][0], pp.x, v0); fma2(acc2[1][0], pp.y, v0);
            fma2(acc2[0][1], pp.x, v1); fma2(acc2[1][1], pp.y, v1);
            fma2(acc2[0][2], pp.x, v2); fma2(acc2[1][2], pp.y, v2);
            fma2(acc2[0][3], pp.x, v3); fma2(acc2[1][3], pp.y, v3);
        }
    }

    // epilogue: normalize and write out[c][p]
#pragma unroll
    for (int r = 0; r < 2; r++)
#pragma unroll
        for (int j = 0; j < 4; j++) {
            float o0, o1;
            unpack2(acc2[r][j], o0, o1);
            int cc = tx * 4 + j;
            out[cc * 9216 + p0 + ty * 4 + 2 * r]     = o0 / l[2 * r];
            out[cc * 9216 + p0 + ty * 4 + 2 * r + 1] = o1 / l[2 * r + 1];
        }
}

// ---------------- launch ----------------
extern "C" void kernel_launch(void* const* d_in, const int* in_sizes, int n_in,
                              void* d_out, int out_size) {
    const float* X        = (const float*)d_in[0];
    const float* WQ_task  = (const float*)d_in[1];
    const float* BQ_task  = (const float*)d_in[2];
    const float* WK_task  = (const float*)d_in[3];
    // d_in[4] = BK_task, d_in[11] = BK: cancel in softmax (row-constant) — unused
    const float* WV_task  = (const float*)d_in[5];
    const float* BV_task  = (const float*)d_in[6];
    const float* WQ_tm1   = (const float*)d_in[7];
    const float* WQ_x     = (const float*)d_in[8];
    const float* BQ       = (const float*)d_in[9];
    const float* WK_x     = (const float*)d_in[10];
    const float* prevQ    = (const float*)d_in[12];
    const float* Vconv_w  = (const float*)d_in[13];
    const float* Vconv_b  = (const float*)d_in[14];
    float* out = (float*)d_out;

    coef_kernel<<<1, 256>>>(WQ_task, BQ_task, WK_task, WQ_tm1, WQ_x, BQ, WK_x);
    qprep_kernel<<<dim3(36, 256), 256>>>(X, prevQ);
    conv_kernel<<<dim3(96, 2), 256>>>(X, Vconv_w, Vconv_b, WV_task, BV_task);

    cudaFuncSetAttribute(attn_kernel,
                         cudaFuncAttributeMaxDynamicSharedMemorySize,
                         ATTN_SMEM_BYTES);
    attn_kernel<<<144, 256, ATTN_SMEM_BYTES>>>(X, out);
}

// round 5
// speedup vs baseline: 1.2955x; 1.2955x over previous
#include <cuda_runtime.h>

#define ULL unsigned long long

// ---------------- scratch (static device allocations) ----------------
__device__ float g_Qp[256 * 9216];   // Q'[f][p] = kA[f] * Qs[f][p]
__device__ float g_V[9216 * 64];     // V[p][c]  (transposed for attn staging)
__device__ float g_cA[8 * 256];
__device__ float g_cB[256];
__device__ float g_cC[256];

// ---------------- packed f32x2 helpers ----------------
__device__ __forceinline__ ULL pack2(float lo, float hi) {
    ULL r;
    asm("mov.b64 %0, {%1, %2};" : "=l"(r)
        : "r"(__float_as_uint(lo)), "r"(__float_as_uint(hi)));
    return r;
}
__device__ __forceinline__ void unpack2(ULL v, float& lo, float& hi) {
    unsigned a, b;
    asm("mov.b64 {%0, %1}, %2;" : "=r"(a), "=r"(b) : "l"(v));
    lo = __uint_as_float(a);
    hi = __uint_as_float(b);
}
__device__ __forceinline__ void fma2(ULL& d, ULL a, ULL b) {
    asm("fma.rn.f32x2 %0, %1, %2, %0;" : "+l"(d) : "l"(a), "l"(b));
}
__device__ __forceinline__ void mul2(ULL& d, ULL a) {
    asm("mul.rn.f32x2 %0, %0, %1;" : "+l"(d) : "l"(a));
}

#define HBAR(id) asm volatile("bar.sync %0, 256;" :: "r"(id) : "memory")

// ---------------- kernel 1: per-feature coefficients ----------------
__global__ void coef_kernel(const float* __restrict__ WQ_task,
                            const float* __restrict__ BQ_task,
                            const float* __restrict__ WK_task,
                            const float* __restrict__ WQ_tm1,
                            const float* __restrict__ WQ_x,
                            const float* __restrict__ BQ,
                            const float* __restrict__ WK_x) {
    int f = threadIdx.x;  // 256 threads
    float kA = WK_task[f] * WK_x[f];
    float sW = 0.f, sB = 0.f;
#pragma unroll
    for (int h = 0; h < 8; h++) {
        float wq = WQ_task[h * 256 + f];
        sW += wq;
        sB += wq * BQ[h * 256 + f] + BQ_task[h * 256 + f];
        g_cA[h * 256 + f] = kA * wq * WQ_tm1[h * 256 + f];
    }
    g_cB[f] = kA * WQ_x[f] * sW;
    g_cC[f] = kA * sB;
}

// ---------------- kernel 2: build Q' ----------------
__global__ void qprep_kernel(const float* __restrict__ X,
                             const float* __restrict__ prevQ) {
    int f = blockIdx.y;
    int p = blockIdx.x * 256 + threadIdx.x;
    float q = fmaf(g_cB[f], X[f * 9216 + p], g_cC[f]);
#pragma unroll
    for (int h = 0; h < 8; h++)
        q = fmaf(g_cA[h * 256 + f], prevQ[(h * 256 + f) * 9216 + p], q);
    g_Qp[f * 9216 + p] = q;
}

// ---------------- kernel 3: 3x3 SAME conv (F=256 -> C=64) + affine ----------------
// writes g_V in [p][c] layout
__global__ void __launch_bounds__(256) conv_kernel(const float* __restrict__ X,
                                                   const float* __restrict__ Wc,
                                                   const float* __restrict__ Bc,
                                                   const float* __restrict__ WV,
                                                   const float* __restrict__ BV) {
    __shared__ float sx[4 * 294];  // [4 f][3 dw][98 h (padded)]
    __shared__ float sw[4 * 288];  // [4 f][32 c][9 taps]
    const int tid = threadIdx.x;
    const int w = blockIdx.x;
    const int cbase = blockIdx.y * 32;
    const int cl = tid >> 3;
    const int c = cbase + cl;
    const int h0 = (tid & 7) * 12;

    float acc[12];
#pragma unroll
    for (int i = 0; i < 12; i++) acc[i] = 0.f;

    for (int fc = 0; fc < 256; fc += 4) {
        __syncthreads();
        for (int i = tid; i < 4 * 294; i += 256) {
            int ff = i / 294, r = i % 294;
            int dw = r / 98, hh = r % 98;
            int ww = w + dw - 1;
            float v = 0.f;
            if (ww >= 0 && ww < 96 && hh >= 1 && hh <= 96)
                v = X[(fc + ff) * 9216 + ww * 96 + hh - 1];
            sx[i] = v;
        }
        for (int i = tid; i < 4 * 288; i += 256) {
            int ff = i / 288, r = i % 288;
            int ccl = r / 9, s = r % 9;
            sw[i] = Wc[((cbase + ccl) * 256 + fc + ff) * 9 + s];
        }
        __syncthreads();
#pragma unroll
        for (int ff = 0; ff < 4; ff++) {
            float wv[9];
#pragma unroll
            for (int s = 0; s < 9; s++) wv[s] = sw[ff * 288 + cl * 9 + s];
#pragma unroll
            for (int dw = 0; dw < 3; dw++) {
                float xr[14];
#pragma unroll
                for (int j = 0; j < 14; j++) xr[j] = sx[ff * 294 + dw * 98 + h0 + j];
#pragma unroll
                for (int hi = 0; hi < 12; hi++)
#pragma unroll
                    for (int dh = 0; dh < 3; dh++)
                        acc[hi] = fmaf(xr[hi + dh], wv[dw * 3 + dh], acc[hi]);
            }
        }
    }
    float wv_ = WV[c], bv_ = BV[c], bc_ = Bc[c];
#pragma unroll
    for (int hi = 0; hi < 12; hi++)
        g_V[(w * 96 + h0 + hi) * 64 + c] = fmaf(wv_, acc[hi] + bc_, bv_);
}

// ---------------- kernel 4: flash attention, fp32, f32x2, 2 engines/CTA ----------------
// grid 144 (one 64-query tile), 512 threads = 2 independent 256-thread halves.
// half h processes key tiles {2i+h}, i=0..71; final exact flash-merge.
// smem floats: sQ 16384 | per-half {sX0 4096, sX1 4096, sPT 4352, sVT 4352}
static const int ATTN_SMEM_FLOATS = 16384 + 2 * 16896;
static const int ATTN_SMEM_BYTES = ATTN_SMEM_FLOATS * 4;

__device__ __forceinline__ void ldg_chunk(const float* __restrict__ X,
                                          int cid, int h, int ll, float4* rv) {
    int kt = 2 * (cid >> 2) + h;
    int fb = (cid & 3) * 64;
    int q0 = kt * 64;
#pragma unroll
    for (int t = 0; t < 4; t++) {
        int idx = ll + t * 256;
        int f = idx >> 4, k4 = (idx & 15) << 2;
        rv[t] = *(const float4*)(X + (fb + f) * 9216 + q0 + k4);
    }
}
__device__ __forceinline__ void sts_chunk(float* dst, int ll, const float4* rv) {
#pragma unroll
    for (int t = 0; t < 4; t++) {
        int idx = ll + t * 256;
        int f = idx >> 4, k4 = (idx & 15) << 2;
        *(float4*)(dst + f * 64 + k4) = rv[t];
    }
}

__global__ void __launch_bounds__(512, 1)
attn_kernel(const float* __restrict__ X, float* __restrict__ out) {
    extern __shared__ float sm[];
    const int tid = threadIdx.x;
    const int h = tid >> 8;          // half id 0/1
    const int ll = tid & 255;        // lane within half
    const int ty = ll >> 4;          // 0..15 (query rows ty*4..+3)
    const int tx = ll & 15;          // 0..15 (key cols / channels tx*4..+3)
    const int bid = h + 1;           // named barrier id
    const int p0 = blockIdx.x * 64;

    float* sQ = sm;
    float* sXh = sm + 16384 + h * 16896;
    float* sXb[2] = { sXh, sXh + 4096 };
    float* sPT = sXh + 8192;
    float* sVT = sXh + 12544;

    // --- prologue: start chunk 0 LDG early, stage sQ tile (all 512 threads) ---
    float4 rv[4];
    ldg_chunk(X, 0, h, ll, rv);

    for (int i = tid; i < 4096; i += 512) {
        int f = i >> 4, q = (i & 15) * 4;
        *(float4*)(sQ + f * 64 + q) = *(const float4*)(g_Qp + f * 9216 + p0 + q);
    }
    __syncthreads();

    sts_chunk(sXb[0], ll, rv);
    ldg_chunk(X, 1, h, ll, rv);
    HBAR(bid);

    ULL acc2[2][4];
#pragma unroll
    for (int r = 0; r < 2; r++)
#pragma unroll
        for (int j = 0; j < 4; j++) acc2[r][j] = 0ULL;
    float m[4], lsum[4];
#pragma unroll
    for (int i = 0; i < 4; i++) { m[i] = -1e30f; lsum[i] = 0.f; }

    for (int it = 0; it < 72; it++) {
        const int kt = 2 * it + h;
        const int q0 = kt * 64;

        ULL S2[2][4];
#pragma unroll
        for (int r = 0; r < 2; r++)
#pragma unroll
            for (int j = 0; j < 4; j++) S2[r][j] = 0ULL;

        for (int fcb = 0; fcb < 4; fcb++) {
            const int c = it * 4 + fcb;
            if (c + 1 < 288) sts_chunk(sXb[(c + 1) & 1], ll, rv);
            if (c + 2 < 288) ldg_chunk(X, c + 2, h, ll, rv);

            const float* sQb = sQ + fcb * 4096;
            const float* sXc = sXb[c & 1];
#pragma unroll 16
            for (int fl = 0; fl < 64; fl++) {
                ulonglong2 a = *(const ulonglong2*)(sQb + fl * 64 + ty * 4);
                float4 b = *(const float4*)(sXc + fl * 64 + tx * 4);
                ULL b0 = pack2(b.x, b.x), b1 = pack2(b.y, b.y);
                ULL b2 = pack2(b.z, b.z), b3 = pack2(b.w, b.w);
                fma2(S2[0][0], a.x, b0); fma2(S2[1][0], a.y, b0);
                fma2(S2[0][1], a.x, b1); fma2(S2[1][1], a.y, b1);
                fma2(S2[0][2], a.x, b2); fma2(S2[1][2], a.y, b2);
                fma2(S2[0][3], a.x, b3); fma2(S2[1][3], a.y, b3);
            }
            if (fcb < 3) HBAR(bid);
        }

        // stage V tile (coalesced read from g_V[p][c], conflict-free store)
#pragma unroll
        for (int t = 0; t < 4; t++) {
            int idx = ll + t * 256;
            int k = idx >> 4, c4 = (idx & 15) << 2;
            float4 v = *(const float4*)(g_V + (q0 + k) * 64 + c4);
            *(float4*)(sVT + k * 68 + c4) = v;
        }

        // ---- online softmax on this half's 64x64 S tile ----
        float s[4][4];
#pragma unroll
        for (int r = 0; r < 2; r++)
#pragma unroll
            for (int j = 0; j < 4; j++)
                unpack2(S2[r][j], s[2 * r][j], s[2 * r + 1][j]);

        float p_[4][4], sc[4];
#pragma unroll
        for (int i = 0; i < 4; i++) {
            float rm = fmaxf(fmaxf(s[i][0], s[i][1]), fmaxf(s[i][2], s[i][3]));
#pragma unroll
            for (int o = 8; o > 0; o >>= 1)
                rm = fmaxf(rm, __shfl_xor_sync(0xffffffffu, rm, o));
            float mn = fmaxf(m[i], rm);
            float r0 = 0.f;
#pragma unroll
            for (int j = 0; j < 4; j++) {
                p_[i][j] = __expf(s[i][j] - mn);
                r0 += p_[i][j];
            }
#pragma unroll
            for (int o = 8; o > 0; o >>= 1)
                r0 += __shfl_xor_sync(0xffffffffu, r0, o);
            sc[i] = __expf(m[i] - mn);
            lsum[i] = fmaf(lsum[i], sc[i], r0);
            m[i] = mn;
        }
        ULL sc2[2] = { pack2(sc[0], sc[1]), pack2(sc[2], sc[3]) };
#pragma unroll
        for (int r = 0; r < 2; r++)
#pragma unroll
            for (int j = 0; j < 4; j++) mul2(acc2[r][j], sc2[r]);

        // write P transposed: sPT[k][q]
#pragma unroll
        for (int j = 0; j < 4; j++) {
            float4 v = make_float4(p_[0][j], p_[1][j], p_[2][j], p_[3][j]);
            *(float4*)(sPT + (tx * 4 + j) * 68 + ty * 4) = v;
        }
        HBAR(bid);  // sPT + sVT ready

        // ---- PV: acc[q][c] += sum_k P[k][q] * V[k][c] ----
#pragma unroll 16
        for (int k = 0; k < 64; k++) {
            ulonglong2 pp = *(const ulonglong2*)(sPT + k * 68 + ty * 4);
            float4 v = *(const float4*)(sVT + k * 68 + tx * 4);
            ULL v0 = pack2(v.x, v.x), v1 = pack2(v.y, v.y);
            ULL v2 = pack2(v.z, v.z), v3 = pack2(v.w, v.w);
            fma2(acc2[0][0], pp.x, v0); fma2(acc2[1][0], pp.y, v0);
            fma2(acc2[0][1], pp.x, v1); fma2(acc2[1][1], pp.y, v1);
            fma2(acc2[0][2], pp.x, v2); fma2(acc2[1][2], pp.y, v2);
            fma2(acc2[0][3], pp.x, v3); fma2(acc2[1][3], pp.y, v3);
        }
        HBAR(bid);  // PV readers done before next kt overwrites sPT/sVT/sX
    }

    // ---- epilogue: merge the two flash states, normalize, write out ----
    __syncthreads();
    float* ex = sm;  // reuse sQ region: 256 threads * 24 floats
    if (h == 1) {
        float* b = ex + ll * 24;
#pragma unroll
        for (int i = 0; i < 4; i++) { b[i] = m[i]; b[4 + i] = lsum[i]; }
#pragma unroll
        for (int r = 0; r < 2; r++)
#pragma unroll
            for (int j = 0; j < 4; j++) {
                float lo, hi;
                unpack2(acc2[r][j], lo, hi);
                b[8 + (r * 4 + j) * 2] = lo;
                b[9 + (r * 4 + j) * 2] = hi;
            }
    }
    __syncthreads();
    if (h == 0) {
        const float* b = ex + ll * 24;
        float w0[4], w1[4], L[4];
#pragma unroll
        for (int i = 0; i < 4; i++) {
            float M = fmaxf(m[i], b[i]);
            w0[i] = __expf(m[i] - M);
            w1[i] = __expf(b[i] - M);
            L[i] = lsum[i] * w0[i] + b[4 + i] * w1[i];
        }
#pragma unroll
        for (int r = 0; r < 2; r++)
#pragma unroll
            for (int j = 0; j < 4; j++) {
                float lo, hi;
                unpack2(acc2[r][j], lo, hi);
                float p1lo = b[8 + (r * 4 + j) * 2];
                float p1hi = b[9 + (r * 4 + j) * 2];
                int i0 = 2 * r, i1 = 2 * r + 1;
                float o0 = (lo * w0[i0] + p1lo * w1[i0]) / L[i0];
                float o1 = (hi * w0[i1] + p1hi * w1[i1]) / L[i1];
                int cc = tx * 4 + j;
                out[cc * 9216 + p0 + ty * 4 + i0] = o0;
                out[cc * 9216 + p0 + ty * 4 + i1] = o1;
            }
    }
}

// ---------------- launch ----------------
extern "C" void kernel_launch(void* const* d_in, const int* in_sizes, int n_in,
                              void* d_out, int out_size) {
    const float* X        = (const float*)d_in[0];
    const float* WQ_task  = (const float*)d_in[1];
    const float* BQ_task  = (const float*)d_in[2];
    const float* WK_task  = (const float*)d_in[3];
    // d_in[4] = BK_task, d_in[11] = BK: row-constant in logits -> cancel in softmax
    const float* WV_task  = (const float*)d_in[5];
    const float* BV_task  = (const float*)d_in[6];
    const float* WQ_tm1   = (const float*)d_in[7];
    const float* WQ_x     = (const float*)d_in[8];
    const float* BQ       = (const float*)d_in[9];
    const float* WK_x     = (const float*)d_in[10];
    const float* prevQ    = (const float*)d_in[12];
    const float* Vconv_w  = (const float*)d_in[13];
    const float* Vconv_b  = (const float*)d_in[14];
    float* out = (float*)d_out;

    coef_kernel<<<1, 256>>>(WQ_task, BQ_task, WK_task, WQ_tm1, WQ_x, BQ, WK_x);
    qprep_kernel<<<dim3(36, 256), 256>>>(X, prevQ);
    conv_kernel<<<dim3(96, 2), 256>>>(X, Vconv_w, Vconv_b, WV_task, BV_task);

    cudaFuncSetAttribute(attn_kernel,
                         cudaFuncAttributeMaxDynamicSharedMemorySize,
                         ATTN_SMEM_BYTES);
    attn_kernel<<<144, 512, ATTN_SMEM_BYTES>>>(X, out);
}